// round 2
// baseline (speedup 1.0000x reference)
#include <cuda_runtime.h>

#define ROWS 16
#define NT   128

typedef unsigned long long u64;

__device__ __forceinline__ u64 ffma2(u64 a, u64 b, u64 c) {
    u64 d;
    asm("fma.rn.f32x2 %0, %1, %2, %3;" : "=l"(d) : "l"(a), "l"(b), "l"(c));
    return d;
}
__device__ __forceinline__ u64 pack2(float x) {
    u64 d; unsigned u = __float_as_uint(x);
    asm("mov.b64 %0, {%1, %2};" : "=l"(d) : "r"(u), "r"(u));
    return d;
}
__device__ __forceinline__ float lo2(u64 d) { return __uint_as_float((unsigned)d); }
__device__ __forceinline__ float hi2(u64 d) { return __uint_as_float((unsigned)(d >> 32)); }
__device__ __forceinline__ float sigm(float x) { return 1.0f / (1.0f + __expf(-x)); }

__global__ __launch_bounds__(NT) void tgn_kernel(
    const int*   __restrict__ n_id,
    const float* __restrict__ memory_,
    const float* __restrict__ pos_mem,
    const float* __restrict__ pos_emb,
    const float* __restrict__ raw_s,
    const float* __restrict__ raw_d,
    const int*   __restrict__ other_s,
    const int*   __restrict__ other_d,
    const int*   __restrict__ t_s,
    const int*   __restrict__ t_d,
    const int*   __restrict__ last_update,
    const float* __restrict__ w_tm, const float* __restrict__ b_tm,
    const float* __restrict__ w_tp, const float* __restrict__ b_tp,
    const float* __restrict__ Wih_m, const float* __restrict__ Whh_m,
    const float* __restrict__ bih_m, const float* __restrict__ bhh_m,
    const float* __restrict__ Wih_p, const float* __restrict__ Whh_p,
    const float* __restrict__ bih_p, const float* __restrict__ bhh_p,
    float* __restrict__ out, int N)
{
    // aggr stored k-major: aggr_sm[k*16 + row]  (512 x 16 fp32 = 32 KB)
    __shared__ float aggr_sm[512 * ROWS];
    // h stored k-major: h_sm[k*16 + row]        (128 x 16 fp32 = 8 KB)
    __shared__ float h_sm[128 * ROWS];

    const int tid  = threadIdx.x;
    const int tgn  = blockIdx.y;          // 0 = memory TGN, 1 = position TGN
    const int row0 = blockIdx.x * ROWS;

    const float* mem = tgn ? pos_mem : memory_;
    const float* Wih = tgn ? Wih_p : Wih_m;
    const float* Whh = tgn ? Whh_p : Whh_m;
    const float* bih = tgn ? bih_p : bih_m;
    const float* bhh = tgn ? bhh_p : bhh_m;
    const float* wt  = tgn ? w_tp : w_tm;
    const float* bt  = tgn ? b_tp : b_tm;

    // ---------------- Phase 1: build selected message into smem ----------------
    {
        const int r  = tid & 15;          // row within tile
        const int kb = tid >> 4;          // 0..7, k stride 8
        const int i  = row0 + r;

        const int nid = n_id[i];
        const int ts  = t_s[i];
        const int td  = t_d[i];
        const bool pick = (ts >= td);
        const int od  = other_d[i];
        const int o   = pick ? other_s[i] : od;
        const int lu  = last_update[nid];
        const float trel = (float)((pick ? ts : td) - lu);

        const float* hrow = mem + (size_t)nid * 128;
        const float* orow = mem + (size_t)o   * 128;
        const float* frow;
        if (tgn == 0) frow = (pick ? raw_s : raw_d) + (size_t)i * 128;
        else          frow = pos_emb + (size_t)(pick ? nid : od) * 128;

        #pragma unroll 4
        for (int kk = kb; kk < 128; kk += 8) {
            float hv = hrow[kk];
            aggr_sm[kk * 16 + r]         = hv;
            h_sm[kk * 16 + r]            = hv;
            aggr_sm[(128 + kk) * 16 + r] = orow[kk];
            aggr_sm[(256 + kk) * 16 + r] = frow[kk];
            aggr_sm[(384 + kk) * 16 + r] = cosf(fmaf(trel, wt[kk], bt[kk]));
        }
    }
    __syncthreads();

    // ---------------- Phase 2: GEMM (gi: K=512, gh: K=128), f32x2 packed -------
    // Thread `tid` owns output columns {tid, tid+128, tid+256} = gates {r, z, n}
    u64 acc[3][8];
    u64 acch[3][8];
    #pragma unroll
    for (int g = 0; g < 3; g++)
        #pragma unroll
        for (int j = 0; j < 8; j++) { acc[g][j] = 0ull; acch[g][j] = 0ull; }

    {
        const float* w0 = Wih + (size_t)tid * 512;
        const float* w1 = w0 + 128 * 512;
        const float* w2 = w1 + 128 * 512;
        const u64* A = (const u64*)aggr_sm;
        #pragma unroll 4
        for (int k = 0; k < 512; k++) {
            u64 p0 = pack2(w0[k]);
            u64 p1 = pack2(w1[k]);
            u64 p2 = pack2(w2[k]);
            const u64* a = A + k * 8;
            #pragma unroll
            for (int j = 0; j < 8; j++) {
                u64 av = a[j];
                acc[0][j] = ffma2(p0, av, acc[0][j]);
                acc[1][j] = ffma2(p1, av, acc[1][j]);
                acc[2][j] = ffma2(p2, av, acc[2][j]);
            }
        }
    }
    {
        const float* v0 = Whh + (size_t)tid * 128;
        const float* v1 = v0 + 128 * 128;
        const float* v2 = v1 + 128 * 128;
        const u64* H = (const u64*)h_sm;
        #pragma unroll 4
        for (int k = 0; k < 128; k++) {
            u64 p0 = pack2(v0[k]);
            u64 p1 = pack2(v1[k]);
            u64 p2 = pack2(v2[k]);
            const u64* a = H + k * 8;
            #pragma unroll
            for (int j = 0; j < 8; j++) {
                u64 av = a[j];
                acch[0][j] = ffma2(p0, av, acch[0][j]);
                acch[1][j] = ffma2(p1, av, acch[1][j]);
                acch[2][j] = ffma2(p2, av, acch[2][j]);
            }
        }
    }

    // ---------------- Epilogue: GRU gates (register-local) ---------------------
    const float bi0 = bih[tid], bi1 = bih[tid + 128], bi2 = bih[tid + 256];
    const float bh0 = bhh[tid], bh1 = bhh[tid + 128], bh2 = bhh[tid + 256];
    float* oz = out + (size_t)tgn * N * 128;

    #pragma unroll
    for (int j = 0; j < 8; j++) {
        float ir[2]  = { lo2(acc[0][j]) + bi0, hi2(acc[0][j]) + bi0 };
        float iz[2]  = { lo2(acc[1][j]) + bi1, hi2(acc[1][j]) + bi1 };
        float in_[2] = { lo2(acc[2][j]) + bi2, hi2(acc[2][j]) + bi2 };
        float hr[2]  = { lo2(acch[0][j]) + bh0, hi2(acch[0][j]) + bh0 };
        float hz[2]  = { lo2(acch[1][j]) + bh1, hi2(acch[1][j]) + bh1 };
        float hn[2]  = { lo2(acch[2][j]) + bh2, hi2(acch[2][j]) + bh2 };
        #pragma unroll
        for (int hf = 0; hf < 2; hf++) {
            const int row = 2 * j + hf;
            float rg = sigm(ir[hf] + hr[hf]);
            float zg = sigm(iz[hf] + hz[hf]);
            float ng = tanhf(fmaf(rg, hn[hf], in_[hf]));
            float hv = h_sm[tid * 16 + row];
            // (1-z)*n + z*h  ==  n + z*(h - n)
            float o_ = fmaf(zg, hv - ng, ng);
            oz[(size_t)(row0 + row) * 128 + tid] = o_;
        }
    }

    // ---------------- last_update output (written once, by TGN 0) --------------
    if (tgn == 0 && tid < ROWS) {
        const int i = row0 + tid;
        const int ts = t_s[i], td = t_d[i];
        out[(size_t)2 * N * 128 + i] = (float)(ts > td ? ts : td);
    }
}

extern "C" void kernel_launch(void* const* d_in, const int* in_sizes, int n_in,
                              void* d_out, int out_size)
{
    const int*   n_id    = (const int*)  d_in[0];
    const float* memory_ = (const float*)d_in[1];
    const float* pos_mem = (const float*)d_in[2];
    const float* pos_emb = (const float*)d_in[3];
    const float* raw_s   = (const float*)d_in[4];
    const float* raw_d   = (const float*)d_in[5];
    const int*   other_s = (const int*)  d_in[6];
    const int*   other_d = (const int*)  d_in[7];
    const int*   t_s     = (const int*)  d_in[8];
    const int*   t_d     = (const int*)  d_in[9];
    const int*   last_up = (const int*)  d_in[10];
    const float* w_tm    = (const float*)d_in[11];
    const float* b_tm    = (const float*)d_in[12];
    const float* w_tp    = (const float*)d_in[13];
    const float* b_tp    = (const float*)d_in[14];
    const float* Wih_m   = (const float*)d_in[15];
    const float* Whh_m   = (const float*)d_in[16];
    const float* bih_m   = (const float*)d_in[17];
    const float* bhh_m   = (const float*)d_in[18];
    const float* Wih_p   = (const float*)d_in[19];
    const float* Whh_p   = (const float*)d_in[20];
    const float* bih_p   = (const float*)d_in[21];
    const float* bhh_p   = (const float*)d_in[22];

    const int N = in_sizes[0];

    dim3 grid(N / ROWS, 2);
    tgn_kernel<<<grid, NT>>>(n_id, memory_, pos_mem, pos_emb, raw_s, raw_d,
                             other_s, other_d, t_s, t_d, last_up,
                             w_tm, b_tm, w_tp, b_tp,
                             Wih_m, Whh_m, bih_m, bhh_m,
                             Wih_p, Whh_p, bih_p, bhh_p,
                             (float*)d_out, N);
}

// round 4
// speedup vs baseline: 4.9592x; 4.9592x over previous
#include <cuda_runtime.h>

#define ROWS 16
#define NT   128

typedef unsigned long long u64;

// Transposed, f32x2-duplicated weights: WT[k*384 + col] = (w, w)
__device__ u64 g_WihT[2][512 * 384];   // 3.1 MB
__device__ u64 g_WhhT[2][128 * 384];   // 0.8 MB

__device__ __forceinline__ u64 ffma2(u64 a, u64 b, u64 c) {
    u64 d;
    asm("fma.rn.f32x2 %0, %1, %2, %3;" : "=l"(d) : "l"(a), "l"(b), "l"(c));
    return d;
}
__device__ __forceinline__ u64 pack2(float x) {
    u64 d; unsigned u = __float_as_uint(x);
    asm("mov.b64 %0, {%1, %2};" : "=l"(d) : "r"(u), "r"(u));
    return d;
}
__device__ __forceinline__ float lo2(u64 d) { return __uint_as_float((unsigned)d); }
__device__ __forceinline__ float hi2(u64 d) { return __uint_as_float((unsigned)(d >> 32)); }
__device__ __forceinline__ float sigm(float x) { return 1.0f / (1.0f + __expf(-x)); }

__global__ void transpose_wih(const float* __restrict__ Wm, const float* __restrict__ Wp) {
    int idx = blockIdx.x * blockDim.x + threadIdx.x;     // over 512*384
    if (idx >= 512 * 384) return;
    int k = idx / 384, c = idx % 384;
    g_WihT[0][idx] = pack2(Wm[c * 512 + k]);
    g_WihT[1][idx] = pack2(Wp[c * 512 + k]);
}
__global__ void transpose_whh(const float* __restrict__ Wm, const float* __restrict__ Wp) {
    int idx = blockIdx.x * blockDim.x + threadIdx.x;     // over 128*384
    if (idx >= 128 * 384) return;
    int k = idx / 384, c = idx % 384;
    g_WhhT[0][idx] = pack2(Wm[c * 128 + k]);
    g_WhhT[1][idx] = pack2(Wp[c * 128 + k]);
}

__global__ __launch_bounds__(NT) void tgn_kernel(
    const int*   __restrict__ n_id,
    const float* __restrict__ memory_,
    const float* __restrict__ pos_mem,
    const float* __restrict__ pos_emb,
    const float* __restrict__ raw_s,
    const float* __restrict__ raw_d,
    const int*   __restrict__ other_s,
    const int*   __restrict__ other_d,
    const int*   __restrict__ t_s,
    const int*   __restrict__ t_d,
    const int*   __restrict__ last_update,
    const float* __restrict__ w_tm, const float* __restrict__ b_tm,
    const float* __restrict__ w_tp, const float* __restrict__ b_tp,
    const float* __restrict__ bih_m, const float* __restrict__ bhh_m,
    const float* __restrict__ bih_p, const float* __restrict__ bhh_p,
    float* __restrict__ out, int N)
{
    // aggr stored k-major: aggr_sm[k*16 + row]  (512 x 16 fp32 = 32 KB)
    // rows [0,128) double as h (first concat component is h itself).
    __shared__ __align__(16) float aggr_sm[512 * ROWS];

    const int tid  = threadIdx.x;
    const int tgn  = blockIdx.y;          // 0 = memory TGN, 1 = position TGN
    const int row0 = blockIdx.x * ROWS;

    const float* mem = tgn ? pos_mem : memory_;
    const float* bih = tgn ? bih_p : bih_m;
    const float* bhh = tgn ? bhh_p : bhh_m;
    const float* wt  = tgn ? w_tp : w_tm;
    const float* bt  = tgn ? b_tp : b_tm;
    const u64* __restrict__ WihT = g_WihT[tgn];
    const u64* __restrict__ WhhT = g_WhhT[tgn];

    // ---------------- Phase 1: build selected message into smem ----------------
    {
        const int r  = tid & 15;          // row within tile
        const int kb = tid >> 4;          // 0..7, k stride 8
        const int i  = row0 + r;

        const int nid = n_id[i];
        const int ts  = t_s[i];
        const int td  = t_d[i];
        const bool pick = (ts >= td);
        const int od  = other_d[i];
        const int o   = pick ? other_s[i] : od;
        const int lu  = last_update[nid];
        const float trel = (float)((pick ? ts : td) - lu);

        const float* hrow = mem + (size_t)nid * 128;
        const float* orow = mem + (size_t)o   * 128;
        const float* frow;
        if (tgn == 0) frow = (pick ? raw_s : raw_d) + (size_t)i * 128;
        else          frow = pos_emb + (size_t)(pick ? nid : od) * 128;

        #pragma unroll 4
        for (int kk = kb; kk < 128; kk += 8) {
            aggr_sm[kk * 16 + r]         = hrow[kk];
            aggr_sm[(128 + kk) * 16 + r] = orow[kk];
            aggr_sm[(256 + kk) * 16 + r] = frow[kk];
            aggr_sm[(384 + kk) * 16 + r] = cosf(fmaf(trel, wt[kk], bt[kk]));
        }
    }
    __syncthreads();

    // ---------------- Phase 2: GEMM (gi: K=512, gh: K=128), f32x2 packed -------
    // Thread `tid` owns output columns {tid, tid+128, tid+256} = gates {r, z, n}
    u64 acc[3][8];
    u64 acch[3][8];
    #pragma unroll
    for (int g = 0; g < 3; g++)
        #pragma unroll
        for (int j = 0; j < 8; j++) { acc[g][j] = 0ull; acch[g][j] = 0ull; }

    {
        const u64* w = WihT + tid;
        const ulonglong2* A = (const ulonglong2*)aggr_sm;
        #pragma unroll 4
        for (int k = 0; k < 512; k++) {
            u64 p0 = w[k * 384];
            u64 p1 = w[k * 384 + 128];
            u64 p2 = w[k * 384 + 256];
            const ulonglong2* a = A + k * 4;
            #pragma unroll
            for (int jj = 0; jj < 4; jj++) {
                ulonglong2 av = a[jj];
                acc[0][2*jj]   = ffma2(p0, av.x, acc[0][2*jj]);
                acc[1][2*jj]   = ffma2(p1, av.x, acc[1][2*jj]);
                acc[2][2*jj]   = ffma2(p2, av.x, acc[2][2*jj]);
                acc[0][2*jj+1] = ffma2(p0, av.y, acc[0][2*jj+1]);
                acc[1][2*jj+1] = ffma2(p1, av.y, acc[1][2*jj+1]);
                acc[2][2*jj+1] = ffma2(p2, av.y, acc[2][2*jj+1]);
            }
        }
    }
    {
        const u64* w = WhhT + tid;
        const ulonglong2* H = (const ulonglong2*)aggr_sm;   // first 128 k-rows = h
        #pragma unroll 4
        for (int k = 0; k < 128; k++) {
            u64 p0 = w[k * 384];
            u64 p1 = w[k * 384 + 128];
            u64 p2 = w[k * 384 + 256];
            const ulonglong2* a = H + k * 4;
            #pragma unroll
            for (int jj = 0; jj < 4; jj++) {
                ulonglong2 av = a[jj];
                acch[0][2*jj]   = ffma2(p0, av.x, acch[0][2*jj]);
                acch[1][2*jj]   = ffma2(p1, av.x, acch[1][2*jj]);
                acch[2][2*jj]   = ffma2(p2, av.x, acch[2][2*jj]);
                acch[0][2*jj+1] = ffma2(p0, av.y, acch[0][2*jj+1]);
                acch[1][2*jj+1] = ffma2(p1, av.y, acch[1][2*jj+1]);
                acch[2][2*jj+1] = ffma2(p2, av.y, acch[2][2*jj+1]);
            }
        }
    }

    // ---------------- Epilogue: GRU gates (register-local) ---------------------
    const float bi0 = bih[tid], bi1 = bih[tid + 128], bi2 = bih[tid + 256];
    const float bh0 = bhh[tid], bh1 = bhh[tid + 128], bh2 = bhh[tid + 256];
    float* oz = out + (size_t)tgn * N * 128;

    #pragma unroll
    for (int j = 0; j < 8; j++) {
        float ir[2]  = { lo2(acc[0][j]) + bi0, hi2(acc[0][j]) + bi0 };
        float iz[2]  = { lo2(acc[1][j]) + bi1, hi2(acc[1][j]) + bi1 };
        float in_[2] = { lo2(acc[2][j]) + bi2, hi2(acc[2][j]) + bi2 };
        float hr[2]  = { lo2(acch[0][j]) + bh0, hi2(acch[0][j]) + bh0 };
        float hz[2]  = { lo2(acch[1][j]) + bh1, hi2(acch[1][j]) + bh1 };
        float hn[2]  = { lo2(acch[2][j]) + bh2, hi2(acch[2][j]) + bh2 };
        #pragma unroll
        for (int hf = 0; hf < 2; hf++) {
            const int row = 2 * j + hf;
            float rg = sigm(ir[hf] + hr[hf]);
            float zg = sigm(iz[hf] + hz[hf]);
            float ng = tanhf(fmaf(rg, hn[hf], in_[hf]));
            float hv = aggr_sm[tid * 16 + row];        // h[row][tid]
            float o_ = fmaf(zg, hv - ng, ng);          // (1-z)*n + z*h
            oz[(size_t)(row0 + row) * 128 + tid] = o_;
        }
    }

    // ---------------- last_update output (written once, by TGN 0) --------------
    if (tgn == 0 && tid < ROWS) {
        const int i = row0 + tid;
        const int ts = t_s[i], td = t_d[i];
        out[(size_t)2 * N * 128 + i] = (float)(ts > td ? ts : td);
    }
}

extern "C" void kernel_launch(void* const* d_in, const int* in_sizes, int n_in,
                              void* d_out, int out_size)
{
    const int*   n_id    = (const int*)  d_in[0];
    const float* memory_ = (const float*)d_in[1];
    const float* pos_mem = (const float*)d_in[2];
    const float* pos_emb = (const float*)d_in[3];
    const float* raw_s   = (const float*)d_in[4];
    const float* raw_d   = (const float*)d_in[5];
    const int*   other_s = (const int*)  d_in[6];
    const int*   other_d = (const int*)  d_in[7];
    const int*   t_s     = (const int*)  d_in[8];
    const int*   t_d     = (const int*)  d_in[9];
    const int*   last_up = (const int*)  d_in[10];
    const float* w_tm    = (const float*)d_in[11];
    const float* b_tm    = (const float*)d_in[12];
    const float* w_tp    = (const float*)d_in[13];
    const float* b_tp    = (const float*)d_in[14];
    const float* Wih_m   = (const float*)d_in[15];
    const float* Whh_m   = (const float*)d_in[16];
    const float* bih_m   = (const float*)d_in[17];
    const float* bhh_m   = (const float*)d_in[18];
    const float* Wih_p   = (const float*)d_in[19];
    const float* Whh_p   = (const float*)d_in[20];
    const float* bih_p   = (const float*)d_in[21];
    const float* bhh_p   = (const float*)d_in[22];

    const int N = in_sizes[0];

    transpose_wih<<<(512 * 384 + 255) / 256, 256>>>(Wih_m, Wih_p);
    transpose_whh<<<(128 * 384 + 255) / 256, 256>>>(Whh_m, Whh_p);

    dim3 grid(N / ROWS, 2);
    tgn_kernel<<<grid, NT>>>(n_id, memory_, pos_mem, pos_emb, raw_s, raw_d,
                             other_s, other_d, t_s, t_d, last_up,
                             w_tm, b_tm, w_tp, b_tp,
                             bih_m, bhh_m, bih_p, bhh_p,
                             (float*)d_out, N);
}

// round 7
// speedup vs baseline: 7.3574x; 1.4836x over previous
#include <cuda_runtime.h>
#include <cuda_bf16.h>
#include <cstdint>

#define NT 512
#define MT 64

// ---- smem byte offsets ----
#define OFF_A     0          // A hi: 64 rows x 1024B; lo at +65536  (131072 total)
#define OFF_B     131072     // 2 buffers x 32768 (hi 16K | lo 16K)
#define OFF_BIAS  196608     // 512 f32 interleaved biases
#define OFF_TREL  198656     // 64 f32
#define OFF_HP    198912     // 64 x 8B ptr
#define OFF_OP    199424
#define OFF_FP    199936
#define OFF_WT    200448     // 128 f32
#define OFF_BT    200960     // 128 f32
#define SMEM_TOTAL 201728

// fused, interleaved, swizzled B image: [tgn][32 chunks][hi 16K | lo 16K]
__device__ unsigned char g_Bimg[2u * 32u * 32768u];

__device__ __forceinline__ uint32_t smem_u32(const void* p) {
    uint32_t a;
    asm("{ .reg .u64 t; cvta.to.shared.u64 t, %1; cvt.u32.u64 %0, t; }" : "=r"(a) : "l"(p));
    return a;
}
__device__ __forceinline__ void cpasync16(uint32_t s, const void* g) {
    asm volatile("cp.async.cg.shared.global [%0], [%1], 16;" :: "r"(s), "l"(g));
}
#define CP_COMMIT() asm volatile("cp.async.commit_group;" ::: "memory")
#define CP_WAIT1()  asm volatile("cp.async.wait_group 1;" ::: "memory")
#define CP_WAIT0()  asm volatile("cp.async.wait_group 0;" ::: "memory")

__device__ __forceinline__ void ldm4(uint32_t* r, uint32_t a) {
    asm volatile("ldmatrix.sync.aligned.m8n8.x4.shared.b16 {%0,%1,%2,%3}, [%4];"
        : "=r"(r[0]), "=r"(r[1]), "=r"(r[2]), "=r"(r[3]) : "r"(a));
}
__device__ __forceinline__ void ldm4t(uint32_t* r, uint32_t a) {
    asm volatile("ldmatrix.sync.aligned.m8n8.x4.trans.shared.b16 {%0,%1,%2,%3}, [%4];"
        : "=r"(r[0]), "=r"(r[1]), "=r"(r[2]), "=r"(r[3]) : "r"(a));
}
__device__ __forceinline__ void mma16816(float* c, const uint32_t* a, uint32_t b0, uint32_t b1) {
    asm volatile("mma.sync.aligned.m16n8k16.row.col.f32.bf16.bf16.f32 "
        "{%0,%1,%2,%3}, {%4,%5,%6,%7}, {%8,%9}, {%0,%1,%2,%3};"
        : "+f"(c[0]), "+f"(c[1]), "+f"(c[2]), "+f"(c[3])
        : "r"(a[0]), "r"(a[1]), "r"(a[2]), "r"(a[3]), "r"(b0), "r"(b1));
}
__device__ __forceinline__ float sigm(float x) { return 1.0f / (1.0f + __expf(-x)); }

// ---- prep: fused, gate-interleaved, swizzled B hi/lo image ----
// col c = 4*u + gate. gate0: Wih_r + Whh_r(k<128); gate1: Wih_z + Whh_z(k<128);
// gate2: Wih_n; gate3: Whh_n (k<128, else 0).
__global__ void prep_B(const float* __restrict__ Wih_m, const float* __restrict__ Whh_m,
                       const float* __restrict__ Wih_p, const float* __restrict__ Whh_p) {
    unsigned gid = blockIdx.x * blockDim.x + threadIdx.x;
    if (gid >= 2u * 32u * 16u * 512u) return;
    int n = gid & 511;
    int kl = (gid >> 9) & 15;
    int chunk = (gid >> 13) & 31;
    int tgn = gid >> 18;
    int k = chunk * 16 + kl;
    int u = n >> 2, g = n & 3;
    const float* Wih = tgn ? Wih_p : Wih_m;
    const float* Whh = tgn ? Whh_p : Whh_m;
    float v;
    if (g == 0)      v = Wih[(size_t)u * 512 + k] + (k < 128 ? Whh[(size_t)u * 128 + k] : 0.0f);
    else if (g == 1) v = Wih[(size_t)(128 + u) * 512 + k] + (k < 128 ? Whh[(size_t)(128 + u) * 128 + k] : 0.0f);
    else if (g == 2) v = Wih[(size_t)(256 + u) * 512 + k];
    else             v = (k < 128) ? Whh[(size_t)(256 + u) * 128 + k] : 0.0f;
    __nv_bfloat16 hi = __float2bfloat16(v);
    __nv_bfloat16 lo = __float2bfloat16(v - __bfloat162float(hi));
    unsigned off = (unsigned)kl * 1024u + (((unsigned)n * 2u) ^ (((unsigned)kl & 7u) << 4));
    size_t base = ((size_t)tgn * 32 + chunk) * 32768u;
    *(__nv_bfloat16*)(g_Bimg + base + off) = hi;
    *(__nv_bfloat16*)(g_Bimg + base + 16384 + off) = lo;
}

__device__ __forceinline__ void issue_chunk(uint32_t smb, int buf,
                                            const unsigned char* img, int chunk, int tid) {
    uint32_t d = smb + OFF_B + buf * 32768 + tid * 16;
    const unsigned char* s = img + (size_t)chunk * 32768u + tid * 16;
    #pragma unroll
    for (int r = 0; r < 4; r++) cpasync16(d + r * 8192, s + r * 8192);
}

__global__ __launch_bounds__(NT, 1) void tgn_hmma_kernel(
    const int* __restrict__ n_id,
    const float* __restrict__ memory_, const float* __restrict__ pos_mem,
    const float* __restrict__ pos_emb,
    const float* __restrict__ raw_s, const float* __restrict__ raw_d,
    const int* __restrict__ other_s, const int* __restrict__ other_d,
    const int* __restrict__ t_s, const int* __restrict__ t_d,
    const int* __restrict__ last_update,
    const float* __restrict__ w_tm, const float* __restrict__ b_tm,
    const float* __restrict__ w_tp, const float* __restrict__ b_tp,
    const float* __restrict__ bih_m, const float* __restrict__ bhh_m,
    const float* __restrict__ bih_p, const float* __restrict__ bhh_p,
    float* __restrict__ out, int N)
{
    extern __shared__ unsigned char sm[];
    const uint32_t smb = smem_u32(sm);
    const int tid = threadIdx.x, wid = tid >> 5, lane = tid & 31;
    const int tgn = blockIdx.y;
    const int row0 = blockIdx.x * MT;

    const float* mem = tgn ? pos_mem : memory_;
    const float* bih = tgn ? bih_p : bih_m;
    const float* bhh = tgn ? bhh_p : bhh_m;
    const float* wt  = tgn ? w_tp : w_tm;
    const float* bt  = tgn ? b_tp : b_tm;
    const unsigned char* img = g_Bimg + (size_t)tgn * 32u * 32768u;

    // ---- phase 0: metadata, biases, time params ----
    if (tid < 64) {
        const int i = row0 + tid;
        const int nid = n_id[i];
        const int ts = t_s[i], td = t_d[i];
        const bool pick = (ts >= td);
        const int od = other_d[i];
        const int o = pick ? other_s[i] : od;
        ((float*)(sm + OFF_TREL))[tid] = (float)((pick ? ts : td) - last_update[nid]);
        ((const float**)(sm + OFF_HP))[tid] = mem + (size_t)nid * 128;
        ((const float**)(sm + OFF_OP))[tid] = mem + (size_t)o * 128;
        const float* f;
        if (tgn == 0) f = (pick ? raw_s : raw_d) + (size_t)i * 128;
        else          f = pos_emb + (size_t)(pick ? nid : od) * 128;
        ((const float**)(sm + OFF_FP))[tid] = f;
    }
    if (tid < 128) {
        ((float*)(sm + OFF_WT))[tid] = wt[tid];
        ((float*)(sm + OFF_BT))[tid] = bt[tid];
    }
    {   // interleaved biases: c = 4u+g
        const int c = tid, u = c >> 2, g = c & 3;
        float bv;
        if (g == 0)      bv = bih[u] + bhh[u];
        else if (g == 1) bv = bih[128 + u] + bhh[128 + u];
        else if (g == 2) bv = bih[256 + u];
        else             bv = bhh[256 + u];
        ((float*)(sm + OFF_BIAS))[c] = bv;
    }

    // prefetch B chunks 0,1
    issue_chunk(smb, 0, img, 0, tid); CP_COMMIT();
    issue_chunk(smb, 1, img, 1, tid); CP_COMMIT();
    __syncthreads();

    // ---- phase 1: build A (bf16 hi/lo, swizzled rows) ----
    {
        const int r = tid & 63;          // row
        const int p = tid >> 6;          // 0..7 -> k block of 64
        const int sec = p >> 1;          // 0:h 1:other 2:feat 3:time
        const int idx0 = (p & 1) * 64;
        const float* src =
            (sec == 0) ? ((const float**)(sm + OFF_HP))[r] :
            (sec == 1) ? ((const float**)(sm + OFF_OP))[r] :
            (sec == 2) ? ((const float**)(sm + OFF_FP))[r] : nullptr;
        const float trel = ((const float*)(sm + OFF_TREL))[r];
        const float* wts = (const float*)(sm + OFF_WT);
        const float* bts = (const float*)(sm + OFF_BT);
        #pragma unroll 4
        for (int kk = 0; kk < 64; kk += 4) {
            const int k = p * 64 + kk;
            float4 v;
            if (sec < 3) v = *(const float4*)(src + idx0 + kk);
            else {
                const int q = idx0 + kk;
                v.x = cosf(fmaf(trel, wts[q + 0], bts[q + 0]));
                v.y = cosf(fmaf(trel, wts[q + 1], bts[q + 1]));
                v.z = cosf(fmaf(trel, wts[q + 2], bts[q + 2]));
                v.w = cosf(fmaf(trel, wts[q + 3], bts[q + 3]));
            }
            __nv_bfloat162 h01 = __floats2bfloat162_rn(v.x, v.y);
            __nv_bfloat162 h23 = __floats2bfloat162_rn(v.z, v.w);
            __nv_bfloat162 l01 = __floats2bfloat162_rn(
                v.x - __bfloat162float(__low2bfloat16(h01)),
                v.y - __bfloat162float(__high2bfloat16(h01)));
            __nv_bfloat162 l23 = __floats2bfloat162_rn(
                v.z - __bfloat162float(__low2bfloat16(h23)),
                v.w - __bfloat162float(__high2bfloat16(h23)));
            const unsigned off = (unsigned)r * 1024u + (((unsigned)k * 2u) ^ (((unsigned)r & 7u) << 4));
            uint2 hv, lv;
            hv.x = *(unsigned*)&h01; hv.y = *(unsigned*)&h23;
            lv.x = *(unsigned*)&l01; lv.y = *(unsigned*)&l23;
            *(uint2*)(sm + OFF_A + off) = hv;
            *(uint2*)(sm + OFF_A + 65536 + off) = lv;
        }
    }
    __syncthreads();

    // ---- mainloop: 32 K-chunks of 16 ----
    const int wr = wid & 1;              // row group (32 rows)
    const int wc = wid >> 1;             // col block (64 cols)
    const int lrow = (lane & 7) + ((lane & 8) ? 8 : 0);
    const int khalf = (lane & 16) ? 16 : 0;

    float acc[2][8][4];
    #pragma unroll
    for (int a = 0; a < 2; a++)
        #pragma unroll
        for (int b = 0; b < 8; b++)
            #pragma unroll
            for (int c = 0; c < 4; c++) acc[a][b][c] = 0.0f;

    for (int ks = 0; ks < 32; ks++) {
        CP_WAIT1();
        __syncthreads();
        const uint32_t bufb = smb + OFF_B + (ks & 1) * 32768;

        uint32_t ah[2][4], al[2][4];
        #pragma unroll
        for (int mf = 0; mf < 2; mf++) {
            const int arow = wr * 32 + mf * 16 + lrow;
            const unsigned aoff = (unsigned)arow * 1024u +
                (((unsigned)(ks * 32 + khalf)) ^ (((unsigned)arow & 7u) << 4));
            ldm4(ah[mf], smb + OFF_A + aoff);
            ldm4(al[mf], smb + OFF_A + 65536 + aoff);
        }
        #pragma unroll
        for (int jj = 0; jj < 4; jj++) {
            const unsigned nbyte = (unsigned)(wc * 64 + jj * 16) * 2u + (unsigned)khalf;
            const unsigned boff = (unsigned)lrow * 1024u + (nbyte ^ (((unsigned)lrow & 7u) << 4));
            uint32_t bh[4], bl[4];
            ldm4t(bh, bufb + boff);
            ldm4t(bl, bufb + 16384 + boff);
            #pragma unroll
            for (int mf = 0; mf < 2; mf++) {
                mma16816(acc[mf][2 * jj],     ah[mf], bh[0], bh[1]);
                mma16816(acc[mf][2 * jj + 1], ah[mf], bh[2], bh[3]);
                mma16816(acc[mf][2 * jj],     ah[mf], bl[0], bl[1]);
                mma16816(acc[mf][2 * jj + 1], ah[mf], bl[2], bl[3]);
                mma16816(acc[mf][2 * jj],     al[mf], bh[0], bh[1]);
                mma16816(acc[mf][2 * jj + 1], al[mf], bh[2], bh[3]);
            }
        }
        __syncthreads();
        if (ks + 2 < 32) issue_chunk(smb, ks & 1, img, ks + 2, tid);
        CP_COMMIT();
    }
    CP_WAIT0();
    __syncthreads();

    // ---- epilogue: GRU gates via lane-pair exchange ----
    {
        const int g = lane >> 2, t = lane & 3;
        float* stg = (float*)(sm + OFF_B);           // 64 x 132 f32 staging
        const float* biasA = (const float*)(sm + OFF_BIAS);
        #pragma unroll
        for (int mf = 0; mf < 2; mf++) {
            const int mbase = wr * 32 + mf * 16;
            #pragma unroll
            for (int j = 0; j < 8; j++) {
                const int c0 = wc * 64 + j * 8 + 2 * t;
                const float b0v = biasA[c0], b1v = biasA[c0 + 1];
                const float v0 = acc[mf][j][0] + b0v;
                const float v1 = acc[mf][j][1] + b1v;
                const float v2 = acc[mf][j][2] + b0v;
                const float v3 = acc[mf][j][3] + b1v;
                const float p0 = __shfl_xor_sync(0xFFFFFFFFu, v0, 1);
                const float p1 = __shfl_xor_sync(0xFFFFFFFFu, v1, 1);
                const float p2 = __shfl_xor_sync(0xFFFFFFFFu, v2, 1);
                const float p3 = __shfl_xor_sync(0xFFFFFFFFu, v3, 1);
                const int m = mbase + g + ((t & 1) ? 8 : 0);
                const int u = wc * 16 + 2 * j + (t >> 1);
                float rv, zv, iv, hnv;
                if (t & 1) { rv = p2; zv = p3; iv = v2; hnv = v3; }
                else       { rv = v0; zv = v1; iv = p0; hnv = p1; }
                const float rg = sigm(rv);
                const float zg = sigm(zv);
                const float ng = tanhf(fmaf(rg, hnv, iv));
                const unsigned hoff = (unsigned)m * 1024u +
                    (((unsigned)u * 2u) ^ (((unsigned)m & 7u) << 4));
                const float h =
                    __bfloat162float(*(const __nv_bfloat16*)(sm + OFF_A + hoff)) +
                    __bfloat162float(*(const __nv_bfloat16*)(sm + OFF_A + 65536 + hoff));
                stg[m * 132 + u] = fmaf(zg, h - ng, ng);
            }
        }
    }
    __syncthreads();

    // coalesced output
    {
        float* og = out + (size_t)tgn * N * 128 + (size_t)row0 * 128;
        const float* stg = (const float*)(sm + OFF_B);
        #pragma unroll 4
        for (int idx = tid; idx < MT * 128; idx += NT)
            og[idx] = stg[(idx >> 7) * 132 + (idx & 127)];
    }
    if (tgn == 0 && tid < 64) {
        const int i = row0 + tid;
        const int ts = t_s[i], td = t_d[i];
        out[(size_t)2 * N * 128 + i] = (float)(ts > td ? ts : td);
    }
}

extern "C" void kernel_launch(void* const* d_in, const int* in_sizes, int n_in,
                              void* d_out, int out_size)
{
    const int*   n_id    = (const int*)  d_in[0];
    const float* memory_ = (const float*)d_in[1];
    const float* pos_mem = (const float*)d_in[2];
    const float* pos_emb = (const float*)d_in[3];
    const float* raw_s   = (const float*)d_in[4];
    const float* raw_d   = (const float*)d_in[5];
    const int*   other_s = (const int*)  d_in[6];
    const int*   other_d = (const int*)  d_in[7];
    const int*   t_s     = (const int*)  d_in[8];
    const int*   t_d     = (const int*)  d_in[9];
    const int*   last_up = (const int*)  d_in[10];
    const float* w_tm    = (const float*)d_in[11];
    const float* b_tm    = (const float*)d_in[12];
    const float* w_tp    = (const float*)d_in[13];
    const float* b_tp    = (const float*)d_in[14];
    const float* Wih_m   = (const float*)d_in[15];
    const float* Whh_m   = (const float*)d_in[16];
    const float* bih_m   = (const float*)d_in[17];
    const float* bhh_m   = (const float*)d_in[18];
    const float* Wih_p   = (const float*)d_in[19];
    const float* Whh_p   = (const float*)d_in[20];
    const float* bih_p   = (const float*)d_in[21];
    const float* bhh_p   = (const float*)d_in[22];

    const int N = in_sizes[0];

    cudaFuncSetAttribute(tgn_hmma_kernel,
                         cudaFuncAttributeMaxDynamicSharedMemorySize, SMEM_TOTAL);

    prep_B<<<(2 * 32 * 16 * 512 + 255) / 256, 256>>>(Wih_m, Whh_m, Wih_p, Whh_p);

    dim3 grid(N / MT, 2);
    tgn_hmma_kernel<<<grid, NT, SMEM_TOTAL>>>(
        n_id, memory_, pos_mem, pos_emb, raw_s, raw_d,
        other_s, other_d, t_s, t_d, last_up,
        w_tm, b_tm, w_tp, b_tp,
        bih_m, bhh_m, bih_p, bhh_p,
        (float*)d_out, N);
}

// round 8
// speedup vs baseline: 14.8374x; 2.0167x over previous
#include <cuda_runtime.h>
#include <cuda_fp16.h>
#include <cstdint>

#define NT 512
#define MT 64

// ---- smem byte offsets ----
#define OFF_A     0          // A fp16: 64 rows x 1024B = 65536
#define OFF_B     65536      // 2 buffers x 32768 (hi 16K | lo 16K)
#define OFF_H     131072     // 64 x 129 f32 exact h = 33024
#define OFF_BIAS  164096     // 512 f32 interleaved biases
#define OFF_TREL  166144     // 64 f32
#define OFF_HP    166400     // 64 x 8B ptr
#define OFF_OP    166912
#define OFF_FP    167424
#define OFF_WT    167936     // 128 f32
#define OFF_BT    168448     // 128 f32
#define SMEM_TOTAL 168960

// fused, interleaved, swizzled B image: [tgn][32 chunks][hi 16K | lo 16K], fp16
__device__ unsigned char g_Bimg[2u * 32u * 32768u];

__device__ __forceinline__ uint32_t smem_u32(const void* p) {
    uint32_t a;
    asm("{ .reg .u64 t; cvta.to.shared.u64 t, %1; cvt.u32.u64 %0, t; }" : "=r"(a) : "l"(p));
    return a;
}
__device__ __forceinline__ void cpasync16(uint32_t s, const void* g) {
    asm volatile("cp.async.cg.shared.global [%0], [%1], 16;" :: "r"(s), "l"(g));
}
#define CP_COMMIT() asm volatile("cp.async.commit_group;" ::: "memory")
#define CP_WAIT1()  asm volatile("cp.async.wait_group 1;" ::: "memory")
#define CP_WAIT0()  asm volatile("cp.async.wait_group 0;" ::: "memory")

__device__ __forceinline__ void ldm4(uint32_t* r, uint32_t a) {
    asm volatile("ldmatrix.sync.aligned.m8n8.x4.shared.b16 {%0,%1,%2,%3}, [%4];"
        : "=r"(r[0]), "=r"(r[1]), "=r"(r[2]), "=r"(r[3]) : "r"(a));
}
__device__ __forceinline__ void ldm4t(uint32_t* r, uint32_t a) {
    asm volatile("ldmatrix.sync.aligned.m8n8.x4.trans.shared.b16 {%0,%1,%2,%3}, [%4];"
        : "=r"(r[0]), "=r"(r[1]), "=r"(r[2]), "=r"(r[3]) : "r"(a));
}
__device__ __forceinline__ void mma16816(float* c, const uint32_t* a, uint32_t b0, uint32_t b1) {
    asm volatile("mma.sync.aligned.m16n8k16.row.col.f32.f16.f16.f32 "
        "{%0,%1,%2,%3}, {%4,%5,%6,%7}, {%8,%9}, {%0,%1,%2,%3};"
        : "+f"(c[0]), "+f"(c[1]), "+f"(c[2]), "+f"(c[3])
        : "r"(a[0]), "r"(a[1]), "r"(a[2]), "r"(a[3]), "r"(b0), "r"(b1));
}
__device__ __forceinline__ float sigm(float x) { return 1.0f / (1.0f + __expf(-x)); }

// ---- prep: fused, gate-interleaved, swizzled B hi/lo fp16 image ----
// col c = 4*u + gate. gate0: Wih_r + Whh_r(k<128); gate1: Wih_z + Whh_z(k<128);
// gate2: Wih_n; gate3: Whh_n (k<128, else 0).
__global__ void prep_B(const float* __restrict__ Wih_m, const float* __restrict__ Whh_m,
                       const float* __restrict__ Wih_p, const float* __restrict__ Whh_p) {
    unsigned gid = blockIdx.x * blockDim.x + threadIdx.x;
    if (gid >= 2u * 32u * 16u * 512u) return;
    int n = gid & 511;
    int kl = (gid >> 9) & 15;
    int chunk = (gid >> 13) & 31;
    int tgn = gid >> 18;
    int k = chunk * 16 + kl;
    int u = n >> 2, g = n & 3;
    const float* Wih = tgn ? Wih_p : Wih_m;
    const float* Whh = tgn ? Whh_p : Whh_m;
    float v;
    if (g == 0)      v = Wih[(size_t)u * 512 + k] + (k < 128 ? Whh[(size_t)u * 128 + k] : 0.0f);
    else if (g == 1) v = Wih[(size_t)(128 + u) * 512 + k] + (k < 128 ? Whh[(size_t)(128 + u) * 128 + k] : 0.0f);
    else if (g == 2) v = Wih[(size_t)(256 + u) * 512 + k];
    else             v = (k < 128) ? Whh[(size_t)(256 + u) * 128 + k] : 0.0f;
    __half hi = __float2half_rn(v);
    __half lo = __float2half_rn(v - __half2float(hi));
    unsigned off = (unsigned)kl * 1024u + (((unsigned)n * 2u) ^ (((unsigned)kl & 7u) << 4));
    size_t base = ((size_t)tgn * 32 + chunk) * 32768u;
    *(__half*)(g_Bimg + base + off) = hi;
    *(__half*)(g_Bimg + base + 16384 + off) = lo;
}

__device__ __forceinline__ void issue_chunk(uint32_t smb, int buf,
                                            const unsigned char* img, int chunk, int tid) {
    uint32_t d = smb + OFF_B + buf * 32768 + tid * 16;
    const unsigned char* s = img + (size_t)chunk * 32768u + tid * 16;
    #pragma unroll
    for (int r = 0; r < 4; r++) cpasync16(d + r * 8192, s + r * 8192);
}

__global__ __launch_bounds__(NT, 1) void tgn_hmma_kernel(
    const int* __restrict__ n_id,
    const float* __restrict__ memory_, const float* __restrict__ pos_mem,
    const float* __restrict__ pos_emb,
    const float* __restrict__ raw_s, const float* __restrict__ raw_d,
    const int* __restrict__ other_s, const int* __restrict__ other_d,
    const int* __restrict__ t_s, const int* __restrict__ t_d,
    const int* __restrict__ last_update,
    const float* __restrict__ w_tm, const float* __restrict__ b_tm,
    const float* __restrict__ w_tp, const float* __restrict__ b_tp,
    const float* __restrict__ bih_m, const float* __restrict__ bhh_m,
    const float* __restrict__ bih_p, const float* __restrict__ bhh_p,
    float* __restrict__ out, int N)
{
    extern __shared__ unsigned char sm[];
    const uint32_t smb = smem_u32(sm);
    const int tid = threadIdx.x, wid = tid >> 5, lane = tid & 31;
    const int tgn = blockIdx.y;
    const int row0 = blockIdx.x * MT;

    const float* mem = tgn ? pos_mem : memory_;
    const float* bih = tgn ? bih_p : bih_m;
    const float* bhh = tgn ? bhh_p : bhh_m;
    const float* wt  = tgn ? w_tp : w_tm;
    const float* bt  = tgn ? b_tp : b_tm;
    const unsigned char* img = g_Bimg + (size_t)tgn * 32u * 32768u;

    // ---- phase 0: metadata, biases, time params ----
    if (tid < 64) {
        const int i = row0 + tid;
        const int nid = n_id[i];
        const int ts = t_s[i], td = t_d[i];
        const bool pick = (ts >= td);
        const int od = other_d[i];
        const int o = pick ? other_s[i] : od;
        ((float*)(sm + OFF_TREL))[tid] = (float)((pick ? ts : td) - last_update[nid]);
        ((const float**)(sm + OFF_HP))[tid] = mem + (size_t)nid * 128;
        ((const float**)(sm + OFF_OP))[tid] = mem + (size_t)o * 128;
        const float* f;
        if (tgn == 0) f = (pick ? raw_s : raw_d) + (size_t)i * 128;
        else          f = pos_emb + (size_t)(pick ? nid : od) * 128;
        ((const float**)(sm + OFF_FP))[tid] = f;
    }
    if (tid < 128) {
        ((float*)(sm + OFF_WT))[tid] = wt[tid];
        ((float*)(sm + OFF_BT))[tid] = bt[tid];
    }
    {   // interleaved biases: c = 4u+g
        const int c = tid, u = c >> 2, g = c & 3;
        float bv;
        if (g == 0)      bv = bih[u] + bhh[u];
        else if (g == 1) bv = bih[128 + u] + bhh[128 + u];
        else if (g == 2) bv = bih[256 + u];
        else             bv = bhh[256 + u];
        if (c < 512) ((float*)(sm + OFF_BIAS))[c] = bv;
    }

    // prefetch B chunks 0,1
    issue_chunk(smb, 0, img, 0, tid); CP_COMMIT();
    issue_chunk(smb, 1, img, 1, tid); CP_COMMIT();
    __syncthreads();

    // ---- phase 1: build A (fp16, swizzled rows) + exact fp32 h ----
    {
        const int r = tid & 63;          // row
        const int p = tid >> 6;          // 0..7 -> k block of 64
        const int sec = p >> 1;          // 0:h 1:other 2:feat 3:time
        const int idx0 = (p & 1) * 64;
        const float* src =
            (sec == 0) ? ((const float**)(sm + OFF_HP))[r] :
            (sec == 1) ? ((const float**)(sm + OFF_OP))[r] :
            (sec == 2) ? ((const float**)(sm + OFF_FP))[r] : nullptr;
        const float trel = ((const float*)(sm + OFF_TREL))[r];
        const float* wts = (const float*)(sm + OFF_WT);
        const float* bts = (const float*)(sm + OFF_BT);
        float* hrow = (float*)(sm + OFF_H) + r * 129 + idx0;
        #pragma unroll 4
        for (int kk = 0; kk < 64; kk += 4) {
            const int k = p * 64 + kk;
            float4 v;
            if (sec < 3) v = *(const float4*)(src + idx0 + kk);
            else {
                const int q = idx0 + kk;
                v.x = cosf(fmaf(trel, wts[q + 0], bts[q + 0]));
                v.y = cosf(fmaf(trel, wts[q + 1], bts[q + 1]));
                v.z = cosf(fmaf(trel, wts[q + 2], bts[q + 2]));
                v.w = cosf(fmaf(trel, wts[q + 3], bts[q + 3]));
            }
            if (sec == 0) {
                hrow[kk] = v.x; hrow[kk + 1] = v.y; hrow[kk + 2] = v.z; hrow[kk + 3] = v.w;
            }
            __half2 h01 = __floats2half2_rn(v.x, v.y);
            __half2 h23 = __floats2half2_rn(v.z, v.w);
            const unsigned off = (unsigned)r * 1024u + (((unsigned)k * 2u) ^ (((unsigned)r & 7u) << 4));
            uint2 hv;
            hv.x = *(unsigned*)&h01; hv.y = *(unsigned*)&h23;
            *(uint2*)(sm + OFF_A + off) = hv;
        }
    }
    __syncthreads();

    // ---- mainloop: 32 K-chunks of 16 ----
    const int wr = wid & 1;              // row group (32 rows)
    const int wc = wid >> 1;             // col block (64 cols)
    const int lrow = lane & 15;
    const int khalf = (lane & 16) ? 16 : 0;   // byte offset (8 k)

    float acc[2][8][4];
    #pragma unroll
    for (int a = 0; a < 2; a++)
        #pragma unroll
        for (int b = 0; b < 8; b++)
            #pragma unroll
            for (int c = 0; c < 4; c++) acc[a][b][c] = 0.0f;

    for (int ks = 0; ks < 32; ks++) {
        CP_WAIT1();
        __syncthreads();
        const uint32_t bufb = smb + OFF_B + (ks & 1) * 32768;

        uint32_t ah[2][4];
        #pragma unroll
        for (int mf = 0; mf < 2; mf++) {
            const int arow = wr * 32 + mf * 16 + lrow;
            const unsigned aoff = (unsigned)arow * 1024u +
                (((unsigned)(ks * 32 + khalf)) ^ (((unsigned)arow & 7u) << 4));
            ldm4(ah[mf], smb + OFF_A + aoff);
        }
        #pragma unroll
        for (int jj = 0; jj < 4; jj++) {
            const unsigned nbyte = (unsigned)(wc * 64 + jj * 16) * 2u + (unsigned)khalf;
            const unsigned boff = (unsigned)lrow * 1024u + (nbyte ^ (((unsigned)lrow & 7u) << 4));
            uint32_t bh[4], bl[4];
            ldm4t(bh, bufb + boff);
            ldm4t(bl, bufb + 16384 + boff);
            #pragma unroll
            for (int mf = 0; mf < 2; mf++) {
                mma16816(acc[mf][2 * jj],     ah[mf], bh[0], bh[1]);
                mma16816(acc[mf][2 * jj + 1], ah[mf], bh[2], bh[3]);
                mma16816(acc[mf][2 * jj],     ah[mf], bl[0], bl[1]);
                mma16816(acc[mf][2 * jj + 1], ah[mf], bl[2], bl[3]);
            }
        }
        __syncthreads();
        if (ks + 2 < 32) issue_chunk(smb, ks & 1, img, ks + 2, tid);
        CP_COMMIT();
    }
    CP_WAIT0();
    __syncthreads();

    // ---- epilogue: GRU gates via lane-pair exchange ----
    {
        const int g = lane >> 2, t = lane & 3;
        float* stg = (float*)(sm + OFF_B);           // 64 x 132 f32 staging
        const float* biasA = (const float*)(sm + OFF_BIAS);
        const float* hsm = (const float*)(sm + OFF_H);
        #pragma unroll
        for (int mf = 0; mf < 2; mf++) {
            const int mbase = wr * 32 + mf * 16;
            #pragma unroll
            for (int j = 0; j < 8; j++) {
                const int c0 = wc * 64 + j * 8 + 2 * t;
                const float b0v = biasA[c0], b1v = biasA[c0 + 1];
                const float v0 = acc[mf][j][0] + b0v;
                const float v1 = acc[mf][j][1] + b1v;
                const float v2 = acc[mf][j][2] + b0v;
                const float v3 = acc[mf][j][3] + b1v;
                const float p0 = __shfl_xor_sync(0xFFFFFFFFu, v0, 1);
                const float p1 = __shfl_xor_sync(0xFFFFFFFFu, v1, 1);
                const float p2 = __shfl_xor_sync(0xFFFFFFFFu, v2, 1);
                const float p3 = __shfl_xor_sync(0xFFFFFFFFu, v3, 1);
                const int m = mbase + g + ((t & 1) ? 8 : 0);
                const int u = wc * 16 + 2 * j + (t >> 1);
                float rv, zv, iv, hnv;
                if (t & 1) { rv = p2; zv = p3; iv = v2; hnv = v3; }
                else       { rv = v0; zv = v1; iv = p0; hnv = p1; }
                const float rg = sigm(rv);
                const float zg = sigm(zv);
                const float ng = tanhf(fmaf(rg, hnv, iv));
                const float h = hsm[m * 129 + u];
                stg[m * 132 + u] = fmaf(zg, h - ng, ng);
            }
        }
    }
    __syncthreads();

    // coalesced output
    {
        float* og = out + (size_t)tgn * N * 128 + (size_t)row0 * 128;
        const float* stg = (const float*)(sm + OFF_B);
        #pragma unroll 4
        for (int idx = tid; idx < MT * 128; idx += NT)
            og[idx] = stg[(idx >> 7) * 132 + (idx & 127)];
    }
    if (tgn == 0 && tid < 64) {
        const int i = row0 + tid;
        const int ts = t_s[i], td = t_d[i];
        out[(size_t)2 * N * 128 + i] = (float)(ts > td ? ts : td);
    }
}

extern "C" void kernel_launch(void* const* d_in, const int* in_sizes, int n_in,
                              void* d_out, int out_size)
{
    const int*   n_id    = (const int*)  d_in[0];
    const float* memory_ = (const float*)d_in[1];
    const float* pos_mem = (const float*)d_in[2];
    const float* pos_emb = (const float*)d_in[3];
    const float* raw_s   = (const float*)d_in[4];
    const float* raw_d   = (const float*)d_in[5];
    const int*   other_s = (const int*)  d_in[6];
    const int*   other_d = (const int*)  d_in[7];
    const int*   t_s     = (const int*)  d_in[8];
    const int*   t_d     = (const int*)  d_in[9];
    const int*   last_up = (const int*)  d_in[10];
    const float* w_tm    = (const float*)d_in[11];
    const float* b_tm    = (const float*)d_in[12];
    const float* w_tp    = (const float*)d_in[13];
    const float* b_tp    = (const float*)d_in[14];
    const float* Wih_m   = (const float*)d_in[15];
    const float* Whh_m   = (const float*)d_in[16];
    const float* bih_m   = (const float*)d_in[17];
    const float* bhh_m   = (const float*)d_in[18];
    const float* Wih_p   = (const float*)d_in[19];
    const float* Whh_p   = (const float*)d_in[20];
    const float* bih_p   = (const float*)d_in[21];
    const float* bhh_p   = (const float*)d_in[22];

    const int N = in_sizes[0];

    cudaFuncSetAttribute(tgn_hmma_kernel,
                         cudaFuncAttributeMaxDynamicSharedMemorySize, SMEM_TOTAL);

    prep_B<<<(2 * 32 * 16 * 512 + 255) / 256, 256>>>(Wih_m, Whh_m, Wih_p, Whh_p);

    dim3 grid(N / MT, 2);
    tgn_hmma_kernel<<<grid, NT, SMEM_TOTAL>>>(
        n_id, memory_, pos_mem, pos_emb, raw_s, raw_d,
        other_s, other_d, t_s, t_d, last_up,
        w_tm, b_tm, w_tp, b_tp,
        bih_m, bhh_m, bih_p, bhh_p,
        (float*)d_out, N);
}

// round 9
// speedup vs baseline: 20.5677x; 1.3862x over previous
#include <cuda_runtime.h>
#include <cuda_fp16.h>
#include <cstdint>

#define NT 512
#define MT 64

// ---- smem byte offsets ----
#define OFF_A     0          // A fp16: 64 rows x 1024B = 65536
#define OFF_B     65536      // 4 ring buffers x 16384
#define OFF_H     131072     // 64 x 129 f32 exact h = 33024
#define OFF_BIAS  164096     // 512 f32 interleaved biases
#define OFF_TREL  166144     // 64 f32
#define OFF_HP    166400     // 64 x 8B ptr
#define OFF_OP    166912
#define OFF_FP    167424
#define OFF_WT    167936     // 128 f32
#define OFF_BT    168448     // 128 f32
#define SMEM_TOTAL 168960

// fused, gate-interleaved, swizzled fp16 B image: [tgn][32 chunks][16K]
__device__ unsigned char g_Bimg[2u * 32u * 16384u];

__device__ __forceinline__ uint32_t smem_u32(const void* p) {
    uint32_t a;
    asm("{ .reg .u64 t; cvta.to.shared.u64 t, %1; cvt.u32.u64 %0, t; }" : "=r"(a) : "l"(p));
    return a;
}
__device__ __forceinline__ void cpasync16(uint32_t s, const void* g) {
    asm volatile("cp.async.cg.shared.global [%0], [%1], 16;" :: "r"(s), "l"(g));
}
#define CP_COMMIT() asm volatile("cp.async.commit_group;" ::: "memory")
#define CP_WAIT2()  asm volatile("cp.async.wait_group 2;" ::: "memory")
#define CP_WAIT0()  asm volatile("cp.async.wait_group 0;" ::: "memory")

__device__ __forceinline__ void ldm4(uint32_t* r, uint32_t a) {
    asm volatile("ldmatrix.sync.aligned.m8n8.x4.shared.b16 {%0,%1,%2,%3}, [%4];"
        : "=r"(r[0]), "=r"(r[1]), "=r"(r[2]), "=r"(r[3]) : "r"(a));
}
__device__ __forceinline__ void ldm4t(uint32_t* r, uint32_t a) {
    asm volatile("ldmatrix.sync.aligned.m8n8.x4.trans.shared.b16 {%0,%1,%2,%3}, [%4];"
        : "=r"(r[0]), "=r"(r[1]), "=r"(r[2]), "=r"(r[3]) : "r"(a));
}
__device__ __forceinline__ void mma16816(float* c, const uint32_t* a, uint32_t b0, uint32_t b1) {
    asm volatile("mma.sync.aligned.m16n8k16.row.col.f32.f16.f16.f32 "
        "{%0,%1,%2,%3}, {%4,%5,%6,%7}, {%8,%9}, {%0,%1,%2,%3};"
        : "+f"(c[0]), "+f"(c[1]), "+f"(c[2]), "+f"(c[3])
        : "r"(a[0]), "r"(a[1]), "r"(a[2]), "r"(a[3]), "r"(b0), "r"(b1));
}
__device__ __forceinline__ float sigm(float x) { return 1.0f / (1.0f + __expf(-x)); }

// ---- prep: fused, gate-interleaved, swizzled fp16 B image ----
// col c = 4*u + gate. gate0: Wih_r + Whh_r(k<128); gate1: Wih_z + Whh_z(k<128);
// gate2: Wih_n; gate3: Whh_n (k<128, else 0).
__global__ void prep_B(const float* __restrict__ Wih_m, const float* __restrict__ Whh_m,
                       const float* __restrict__ Wih_p, const float* __restrict__ Whh_p) {
    unsigned gid = blockIdx.x * blockDim.x + threadIdx.x;
    if (gid >= 2u * 32u * 16u * 512u) return;
    int n = gid & 511;
    int kl = (gid >> 9) & 15;
    int chunk = (gid >> 13) & 31;
    int tgn = gid >> 18;
    int k = chunk * 16 + kl;
    int u = n >> 2, g = n & 3;
    const float* Wih = tgn ? Wih_p : Wih_m;
    const float* Whh = tgn ? Whh_p : Whh_m;
    float v;
    if (g == 0)      v = Wih[(size_t)u * 512 + k] + (k < 128 ? Whh[(size_t)u * 128 + k] : 0.0f);
    else if (g == 1) v = Wih[(size_t)(128 + u) * 512 + k] + (k < 128 ? Whh[(size_t)(128 + u) * 128 + k] : 0.0f);
    else if (g == 2) v = Wih[(size_t)(256 + u) * 512 + k];
    else             v = (k < 128) ? Whh[(size_t)(256 + u) * 128 + k] : 0.0f;
    unsigned off = (unsigned)kl * 1024u + (((unsigned)n * 2u) ^ (((unsigned)kl & 7u) << 4));
    size_t base = ((size_t)tgn * 32 + chunk) * 16384u;
    *(__half*)(g_Bimg + base + off) = __float2half_rn(v);
}

__device__ __forceinline__ void issue_chunk(uint32_t smb, int slot,
                                            const unsigned char* img, int chunk, int tid) {
    uint32_t d = smb + OFF_B + slot * 16384 + tid * 16;
    const unsigned char* s = img + (size_t)chunk * 16384u + tid * 16;
    #pragma unroll
    for (int r = 0; r < 2; r++) cpasync16(d + r * 8192, s + r * 8192);
}

__global__ __launch_bounds__(NT, 1) void tgn_hmma_kernel(
    const int* __restrict__ n_id,
    const float* __restrict__ memory_, const float* __restrict__ pos_mem,
    const float* __restrict__ pos_emb,
    const float* __restrict__ raw_s, const float* __restrict__ raw_d,
    const int* __restrict__ other_s, const int* __restrict__ other_d,
    const int* __restrict__ t_s, const int* __restrict__ t_d,
    const int* __restrict__ last_update,
    const float* __restrict__ w_tm, const float* __restrict__ b_tm,
    const float* __restrict__ w_tp, const float* __restrict__ b_tp,
    const float* __restrict__ bih_m, const float* __restrict__ bhh_m,
    const float* __restrict__ bih_p, const float* __restrict__ bhh_p,
    float* __restrict__ out, int N)
{
    extern __shared__ unsigned char sm[];
    const uint32_t smb = smem_u32(sm);
    const int tid = threadIdx.x, wid = tid >> 5, lane = tid & 31;
    const int tgn = blockIdx.y;
    const int row0 = blockIdx.x * MT;

    const float* mem = tgn ? pos_mem : memory_;
    const float* bih = tgn ? bih_p : bih_m;
    const float* bhh = tgn ? bhh_p : bhh_m;
    const float* wt  = tgn ? w_tp : w_tm;
    const float* bt  = tgn ? b_tp : b_tm;
    const unsigned char* img = g_Bimg + (size_t)tgn * 32u * 16384u;

    // ---- phase 0: metadata, biases, time params ----
    if (tid < 64) {
        const int i = row0 + tid;
        const int nid = n_id[i];
        const int ts = t_s[i], td = t_d[i];
        const bool pick = (ts >= td);
        const int od = other_d[i];
        const int o = pick ? other_s[i] : od;
        ((float*)(sm + OFF_TREL))[tid] = (float)((pick ? ts : td) - last_update[nid]);
        ((const float**)(sm + OFF_HP))[tid] = mem + (size_t)nid * 128;
        ((const float**)(sm + OFF_OP))[tid] = mem + (size_t)o * 128;
        const float* f;
        if (tgn == 0) f = (pick ? raw_s : raw_d) + (size_t)i * 128;
        else          f = pos_emb + (size_t)(pick ? nid : od) * 128;
        ((const float**)(sm + OFF_FP))[tid] = f;
    }
    if (tid < 128) {
        ((float*)(sm + OFF_WT))[tid] = wt[tid];
        ((float*)(sm + OFF_BT))[tid] = bt[tid];
    }
    {   // interleaved biases: c = 4u+g
        const int c = tid, u = c >> 2, g = c & 3;
        float bv;
        if (g == 0)      bv = bih[u] + bhh[u];
        else if (g == 1) bv = bih[128 + u] + bhh[128 + u];
        else if (g == 2) bv = bih[256 + u];
        else             bv = bhh[256 + u];
        if (c < 512) ((float*)(sm + OFF_BIAS))[c] = bv;
    }

    // prefetch B chunks 0,1,2 into ring slots 0,1,2
    issue_chunk(smb, 0, img, 0, tid); CP_COMMIT();
    issue_chunk(smb, 1, img, 1, tid); CP_COMMIT();
    issue_chunk(smb, 2, img, 2, tid); CP_COMMIT();
    __syncthreads();

    // ---- phase 1: build A (fp16, swizzled rows) + exact fp32 h ----
    {
        const int r = tid & 63;          // row
        const int p = tid >> 6;          // 0..7 -> k block of 64
        const int sec = p >> 1;          // 0:h 1:other 2:feat 3:time
        const int idx0 = (p & 1) * 64;
        const float* src =
            (sec == 0) ? ((const float**)(sm + OFF_HP))[r] :
            (sec == 1) ? ((const float**)(sm + OFF_OP))[r] :
            (sec == 2) ? ((const float**)(sm + OFF_FP))[r] : nullptr;
        const float trel = ((const float*)(sm + OFF_TREL))[r];
        const float* wts = (const float*)(sm + OFF_WT);
        const float* bts = (const float*)(sm + OFF_BT);
        float* hrow = (float*)(sm + OFF_H) + r * 129 + idx0;
        #pragma unroll 4
        for (int kk = 0; kk < 64; kk += 4) {
            const int k = p * 64 + kk;
            float4 v;
            if (sec < 3) v = *(const float4*)(src + idx0 + kk);
            else {
                const int q = idx0 + kk;
                v.x = cosf(fmaf(trel, wts[q + 0], bts[q + 0]));
                v.y = cosf(fmaf(trel, wts[q + 1], bts[q + 1]));
                v.z = cosf(fmaf(trel, wts[q + 2], bts[q + 2]));
                v.w = cosf(fmaf(trel, wts[q + 3], bts[q + 3]));
            }
            if (sec == 0) {
                hrow[kk] = v.x; hrow[kk + 1] = v.y; hrow[kk + 2] = v.z; hrow[kk + 3] = v.w;
            }
            __half2 h01 = __floats2half2_rn(v.x, v.y);
            __half2 h23 = __floats2half2_rn(v.z, v.w);
            const unsigned off = (unsigned)r * 1024u + (((unsigned)k * 2u) ^ (((unsigned)r & 7u) << 4));
            uint2 hv;
            hv.x = *(unsigned*)&h01; hv.y = *(unsigned*)&h23;
            *(uint2*)(sm + OFF_A + off) = hv;
        }
    }
    __syncthreads();

    // ---- mainloop: 32 K-chunks of 16, 4-slot ring, 1 barrier/chunk ----
    const int wr = wid & 1;              // row group (32 rows)
    const int wc = wid >> 1;             // col block (64 cols)
    const int lrow = lane & 15;
    const int khalf = (lane & 16) ? 16 : 0;   // byte offset (8 k)

    float acc[2][8][4];
    #pragma unroll
    for (int a = 0; a < 2; a++)
        #pragma unroll
        for (int b = 0; b < 8; b++)
            #pragma unroll
            for (int c = 0; c < 4; c++) acc[a][b][c] = 0.0f;

    for (int ks = 0; ks < 32; ks++) {
        CP_WAIT2();                       // chunk ks resident
        __syncthreads();                  // all warps done with slot (ks+3)&3's old data
        const uint32_t bufb = smb + OFF_B + (ks & 3) * 16384;

        uint32_t ah[2][4];
        #pragma unroll
        for (int mf = 0; mf < 2; mf++) {
            const int arow = wr * 32 + mf * 16 + lrow;
            const unsigned aoff = (unsigned)arow * 1024u +
                (((unsigned)(ks * 32 + khalf)) ^ (((unsigned)arow & 7u) << 4));
            ldm4(ah[mf], smb + OFF_A + aoff);
        }
        #pragma unroll
        for (int jj = 0; jj < 4; jj++) {
            const unsigned nbyte = (unsigned)(wc * 64 + jj * 16) * 2u + (unsigned)khalf;
            const unsigned boff = (unsigned)lrow * 1024u + (nbyte ^ (((unsigned)lrow & 7u) << 4));
            uint32_t bh[4];
            ldm4t(bh, bufb + boff);
            #pragma unroll
            for (int mf = 0; mf < 2; mf++) {
                mma16816(acc[mf][2 * jj],     ah[mf], bh[0], bh[1]);
                mma16816(acc[mf][2 * jj + 1], ah[mf], bh[2], bh[3]);
            }
        }
        if (ks + 3 < 32) issue_chunk(smb, (ks + 3) & 3, img, ks + 3, tid);
        CP_COMMIT();                      // uniform group counting (empty groups ok)
    }
    CP_WAIT0();
    __syncthreads();

    // ---- epilogue: GRU gates via lane-pair exchange ----
    {
        const int g = lane >> 2, t = lane & 3;
        float* stg = (float*)(sm + OFF_B);           // 64 x 132 f32 staging
        const float* biasA = (const float*)(sm + OFF_BIAS);
        const float* hsm = (const float*)(sm + OFF_H);
        #pragma unroll
        for (int mf = 0; mf < 2; mf++) {
            const int mbase = wr * 32 + mf * 16;
            #pragma unroll
            for (int j = 0; j < 8; j++) {
                const int c0 = wc * 64 + j * 8 + 2 * t;
                const float b0v = biasA[c0], b1v = biasA[c0 + 1];
                const float v0 = acc[mf][j][0] + b0v;
                const float v1 = acc[mf][j][1] + b1v;
                const float v2 = acc[mf][j][2] + b0v;
                const float v3 = acc[mf][j][3] + b1v;
                const float p0 = __shfl_xor_sync(0xFFFFFFFFu, v0, 1);
                const float p1 = __shfl_xor_sync(0xFFFFFFFFu, v1, 1);
                const float p2 = __shfl_xor_sync(0xFFFFFFFFu, v2, 1);
                const float p3 = __shfl_xor_sync(0xFFFFFFFFu, v3, 1);
                const int m = mbase + g + ((t & 1) ? 8 : 0);
                const int u = wc * 16 + 2 * j + (t >> 1);
                float rv, zv, iv, hnv;
                if (t & 1) { rv = p2; zv = p3; iv = v2; hnv = v3; }
                else       { rv = v0; zv = v1; iv = p0; hnv = p1; }
                const float rg = sigm(rv);
                const float zg = sigm(zv);
                const float ng = tanhf(fmaf(rg, hnv, iv));
                const float h = hsm[m * 129 + u];
                stg[m * 132 + u] = fmaf(zg, h - ng, ng);
            }
        }
    }
    __syncthreads();

    // coalesced output
    {
        float* og = out + (size_t)tgn * N * 128 + (size_t)row0 * 128;
        const float* stg = (const float*)(sm + OFF_B);
        #pragma unroll 4
        for (int idx = tid; idx < MT * 128; idx += NT)
            og[idx] = stg[(idx >> 7) * 132 + (idx & 127)];
    }
    if (tgn == 0 && tid < 64) {
        const int i = row0 + tid;
        const int ts = t_s[i], td = t_d[i];
        out[(size_t)2 * N * 128 + i] = (float)(ts > td ? ts : td);
    }
}

extern "C" void kernel_launch(void* const* d_in, const int* in_sizes, int n_in,
                              void* d_out, int out_size)
{
    const int*   n_id    = (const int*)  d_in[0];
    const float* memory_ = (const float*)d_in[1];
    const float* pos_mem = (const float*)d_in[2];
    const float* pos_emb = (const float*)d_in[3];
    const float* raw_s   = (const float*)d_in[4];
    const float* raw_d   = (const float*)d_in[5];
    const int*   other_s = (const int*)  d_in[6];
    const int*   other_d = (const int*)  d_in[7];
    const int*   t_s     = (const int*)  d_in[8];
    const int*   t_d     = (const int*)  d_in[9];
    const int*   last_up = (const int*)  d_in[10];
    const float* w_tm    = (const float*)d_in[11];
    const float* b_tm    = (const float*)d_in[12];
    const float* w_tp    = (const float*)d_in[13];
    const float* b_tp    = (const float*)d_in[14];
    const float* Wih_m   = (const float*)d_in[15];
    const float* Whh_m   = (const float*)d_in[16];
    const float* bih_m   = (const float*)d_in[17];
    const float* bhh_m   = (const float*)d_in[18];
    const float* Wih_p   = (const float*)d_in[19];
    const float* Whh_p   = (const float*)d_in[20];
    const float* bih_p   = (const float*)d_in[21];
    const float* bhh_p   = (const float*)d_in[22];

    const int N = in_sizes[0];

    cudaFuncSetAttribute(tgn_hmma_kernel,
                         cudaFuncAttributeMaxDynamicSharedMemorySize, SMEM_TOTAL);

    prep_B<<<(2 * 32 * 16 * 512 + 255) / 256, 256>>>(Wih_m, Whh_m, Wih_p, Whh_p);

    dim3 grid(N / MT, 2);
    tgn_hmma_kernel<<<grid, NT, SMEM_TOTAL>>>(
        n_id, memory_, pos_mem, pos_emb, raw_s, raw_d,
        other_s, other_d, t_s, t_d, last_up,
        w_tm, b_tm, w_tp, b_tp,
        bih_m, bhh_m, bih_p, bhh_p,
        (float*)d_out, N);
}